// round 9
// baseline (speedup 1.0000x reference)
#include <cuda_runtime.h>
#include <math.h>

#define B_   16
#define N_   2048
#define K_   16
#define EPS_ 1e-8f

// Output layout (tuple flattened in order):
//   psi_prime : B*N*2  floats  @ 0
//   features  : B*N*5  floats  @ 65536
//   knn_idx   : B*N*16 floats  @ 229376
#define PSI_OFF  0
#define FEAT_OFF (B_ * N_ * 2)
#define KNN_OFF  (B_ * N_ * 2 + B_ * N_ * 5)

typedef unsigned long long u64;
typedef unsigned int u32;

#define SENT 0xFFFFFFFFFFFFFFFFull
#define NSPLIT 4               // threads per query
#define SUB_ (N_ / NSPLIT)     // candidates per thread (512)
#define NWIN (SUB_ / 8)        // 8-candidate windows per thread (64)

// SOA candidate data for the KNN kernel.
__device__ float g_x [B_ * N_];
__device__ float g_y [B_ * N_];
__device__ float g_sq[B_ * N_];

// ---------------------------------------------------------------------------
// Kernel 1: features + encoder (tiny MLP) + SOA coord scratch.
// ---------------------------------------------------------------------------
__global__ void encode_kernel(const float* __restrict__ coords,
                              const float* __restrict__ demands,
                              const float* __restrict__ capacity,
                              const float* __restrict__ Wa,
                              const float* __restrict__ ba,
                              const float* __restrict__ W1,
                              const float* __restrict__ b1,
                              const float* __restrict__ W2,
                              const float* __restrict__ b2,
                              float* __restrict__ out)
{
    int b = blockIdx.y;
    int n = blockIdx.x * blockDim.x + threadIdx.x;
    if (n >= N_) return;

    __shared__ float sWa[10], sba[2], sW1[80], sb1[16], sW2[16], sb2_s;
    int t = threadIdx.x;
    if (t < 10) sWa[t] = Wa[t];
    if (t < 2)  sba[t] = ba[t];
    if (t < 80) sW1[t] = W1[t];
    if (t < 16) { sb1[t] = b1[t]; sW2[t] = W2[t]; }
    if (t == 0) sb2_s = b2[0];
    __syncthreads();

    const float* cp = coords + ((long long)b * N_ + n) * 2;
    float x = cp[0], y = cp[1];

    // SOA scratch for knn; sq = rn(rn(x*x) + rn(y*y)) (reference rounding)
    float sq = __fadd_rn(__fmul_rn(x, x), __fmul_rn(y, y));
    g_x [b * N_ + n] = x;
    g_y [b * N_ + n] = y;
    g_sq[b * N_ + n] = sq;

    float dx0 = coords[(long long)b * N_ * 2 + 0];
    float dy0 = coords[(long long)b * N_ * 2 + 1];
    float rx = x - dx0, ry = y - dy0;
    float dist = sqrtf(rx * rx + ry * ry + EPS_);
    float ang  = atan2f(ry, rx);
    float dem  = demands[(long long)b * N_ + n] / capacity[b];

    float f0 = x, f1 = y, f2 = dem, f3 = dist, f4 = ang;

    float* fo = out + FEAT_OFF + ((long long)b * N_ + n) * 5;
    fo[0] = f0; fo[1] = f1; fo[2] = f2; fo[3] = f3; fo[4] = f4;

    float p0 = sba[0] + f0*sWa[0] + f1*sWa[1] + f2*sWa[2] + f3*sWa[3] + f4*sWa[4];
    float p1 = sba[1] + f0*sWa[5] + f1*sWa[6] + f2*sWa[7] + f3*sWa[8] + f4*sWa[9];
    float nrm = sqrtf(p0 * p0 + p1 * p1);
    float inv = 1.0f / (nrm + EPS_);
    p0 *= inv; p1 *= inv;

    float theta = sb2_s;
    #pragma unroll
    for (int h = 0; h < 16; ++h) {
        const float* w = sW1 + h * 5;
        float a = sb1[h] + f0*w[0] + f1*w[1] + f2*w[2] + f3*w[3] + f4*w[4];
        theta += tanhf(a) * sW2[h];
    }
    float c = cosf(theta), s = sinf(theta);

    float* po = out + PSI_OFF + ((long long)b * N_ + n) * 2;
    po[0] = c * p0 - s * p1;
    po[1] = s * p0 + c * p1;
}

// ---------------------------------------------------------------------------
// KNN helpers
// ---------------------------------------------------------------------------

// Monotone map: float bits -> u32 whose unsigned order == float order.
__device__ __forceinline__ u32 fmap(u32 b) {
    return b ^ ((u32)((int)b >> 31) | 0x80000000u);
}

// Flush: convert raw (f32bits<<32|j) buffer entries to total-order keys,
// bitonic-sort-16, merge into sorted L (min-pair + clean), tighten tau.
// Exact ties: keys are (fmap(d2), j) lexicographic. (R7-proven.)
__device__ __forceinline__ void flush16(u64* L, const u64* lbuf, int& n,
                                        float& tau_f)
{
    u64 s[16];
    #pragma unroll
    for (int i = 0; i < 16; ++i) {
        u64 raw = lbuf[i];
        u64 key = ((u64)fmap((u32)(raw >> 32)) << 32) | (u32)raw;
        s[i] = (i < n) ? key : SENT;
    }

    // Bitonic sort 16, ascending.
    #pragma unroll
    for (int k = 2; k <= 16; k <<= 1) {
        #pragma unroll
        for (int j = k >> 1; j > 0; j >>= 1) {
            #pragma unroll
            for (int i = 0; i < 16; ++i) {
                int l = i ^ j;
                if (l > i) {
                    bool up = ((i & k) == 0);
                    u64 a = s[i], b = s[l];
                    bool sw = up ? (a > b) : (a < b);
                    s[i] = sw ? b : a;
                    s[l] = sw ? a : b;
                }
            }
        }
    }

    // Lowest 16 of (L asc, s asc): min-pair -> bitonic, then clean.
    #pragma unroll
    for (int i = 0; i < 16; ++i) {
        u64 a = L[i], b = s[15 - i];
        L[i] = (a < b) ? a : b;
    }
    #pragma unroll
    for (int j = 8; j > 0; j >>= 1) {
        #pragma unroll
        for (int i = 0; i < 16; ++i) {
            int l = i ^ j;
            if (l > i) {
                u64 a = L[i], b = L[l];
                bool sw = a > b;
                L[i] = sw ? b : a;
                L[l] = sw ? a : b;
            }
        }
    }

    // tau = d2 of current 16th (inverse fmap). L is fully real by the first
    // flush (tau=inf until then, so the first 16 candidates all appended).
    u32 h = (u32)(L[15] >> 32);
    h = (h & 0x80000000u) ? (h ^ 0x80000000u) : ~h;
    tau_f = __uint_as_float(h);
    n = 0;
}

// d2 bit-exact with the reference:
//   t = rn(xq*xj); dot = fma(yq,yj,t); s = rn(sqq+sqj)
//   ref rn(s - rn(2*dot)) == rn(s - 2*dot) == fma(-2, dot, s)   [2*dot exact]
#define D2_OF(xv, yv, sv) \
    __fmaf_rn(-2.0f, __fmaf_rn(yq, (yv), __fmul_rn(xq, (xv))), \
              __fadd_rn(sqq, (sv)))

// ---------------------------------------------------------------------------
// Kernel 2: KNN top-16, buffered deferred selection, 4 threads per query.
// Thread p of a query scans quarter [p*512, (p+1)*512), unroll 8, SOA float4
// loads. Local top-16 per thread, but the append gate tau is SHARED across
// the 4 partner lanes (min-reduced after every flush): global-16th <= every
// local-16th and tau only tightens, so no final-top-16 candidate is ever
// dropped; the end merge takes the lowest-16 of the union of appended items.
// Final merge: two stages (shfl xor 1, xor 2) of the R7-proven min-pair +
// bitonic-clean network; all 4 lanes converge, each writes 4 outputs.
// ---------------------------------------------------------------------------
__global__ void __launch_bounds__(128, 6)
knn_kernel(float* __restrict__ out_knn)
{
    int qid = blockIdx.x * 32 + (threadIdx.x >> 2);  // global query id
    int p   = threadIdx.x & 3;                       // candidate-quarter
    int b   = qid >> 11;
    int q   = qid & (N_ - 1);

    const float* bx = g_x  + b * N_;
    const float* by = g_y  + b * N_;
    const float* bs = g_sq + b * N_;

    float xq  = __ldg(&bx[q]);
    float yq  = __ldg(&by[q]);
    float sqq = __ldg(&bs[q]);

    const float4* x4 = (const float4*)(bx + p * SUB_);
    const float4* y4 = (const float4*)(by + p * SUB_);
    const float4* s4 = (const float4*)(bs + p * SUB_);
    int jbase = p * SUB_;

    u64 L[16];
    #pragma unroll
    for (int k = 0; k < 16; ++k) L[k] = SENT;

    u64 lbuf[16];
    int n = 0;
    float tau_f = 3.4e38f;

    #define TRY_APPEND(ev, jv) \
        do { if ((ev) <= tau_f) \
            lbuf[n++] = ((u64)__float_as_uint(ev) << 32) | (u32)(jv); } while (0)

    for (int i = 0; i < NWIN; ++i) {
        float4 xa = __ldg(&x4[2 * i]);
        float4 xb = __ldg(&x4[2 * i + 1]);
        float4 ya = __ldg(&y4[2 * i]);
        float4 yb = __ldg(&y4[2 * i + 1]);
        float4 sa = __ldg(&s4[2 * i]);
        float4 sb = __ldg(&s4[2 * i + 1]);

        float e0 = D2_OF(xa.x, ya.x, sa.x);
        float e1 = D2_OF(xa.y, ya.y, sa.y);
        float e2 = D2_OF(xa.z, ya.z, sa.z);
        float e3 = D2_OF(xa.w, ya.w, sa.w);
        float e4 = D2_OF(xb.x, yb.x, sb.x);
        float e5 = D2_OF(xb.y, yb.y, sb.y);
        float e6 = D2_OF(xb.z, yb.z, sb.z);
        float e7 = D2_OF(xb.w, yb.w, sb.w);

        int j0 = jbase + 8 * i;
        // self-exclusion, one rare branch per 8-window
        if ((unsigned)(q - j0) < 8u) {
            int r = q - j0;
            if (r == 0) e0 = 2.0e30f;  if (r == 1) e1 = 2.0e30f;
            if (r == 2) e2 = 2.0e30f;  if (r == 3) e3 = 2.0e30f;
            if (r == 4) e4 = 2.0e30f;  if (r == 5) e5 = 2.0e30f;
            if (r == 6) e6 = 2.0e30f;  if (r == 7) e7 = 2.0e30f;
        }

        // '<=' so equal-d2/smaller-j candidates always enter; the u64-key
        // flush resolves ties exactly (top_k stable order).
        TRY_APPEND(e0, j0);     TRY_APPEND(e1, j0 + 1);
        TRY_APPEND(e2, j0 + 2); TRY_APPEND(e3, j0 + 3);
        TRY_APPEND(e4, j0 + 4); TRY_APPEND(e5, j0 + 5);
        TRY_APPEND(e6, j0 + 6); TRY_APPEND(e7, j0 + 7);

        // n <= 8 at entry, +8 -> 16 max: no overflow of lbuf[16].
        // Warp-synchronized flush keeps lanes aligned for the shfls below.
        if (__ballot_sync(0xffffffffu, n >= 9)) {
            flush16(L, lbuf, n, tau_f);
            // share tau across the 4 partner lanes (valid upper bound on
            // the global 16th; admits everything the final merge needs)
            float t1 = fminf(tau_f, __shfl_xor_sync(0xffffffffu, tau_f, 1));
            tau_f    = fminf(t1,   __shfl_xor_sync(0xffffffffu, t1,    2));
        }
    }

    flush16(L, lbuf, n, tau_f);   // drain

    // Merge the 4 partner quarters: stage s merges lists lane<->lane^s.
    #pragma unroll
    for (int s = 1; s <= 2; s <<= 1) {
        #pragma unroll
        for (int i = 0; i < 16; ++i) {
            u64 other = __shfl_xor_sync(0xffffffffu, L[15 - i], s);
            u64 a = L[i];
            L[i] = (a < other) ? a : other;
        }
        #pragma unroll
        for (int j = 8; j > 0; j >>= 1) {
            #pragma unroll
            for (int i = 0; i < 16; ++i) {
                int l = i ^ j;
                if (l > i) {
                    u64 a = L[i], b2 = L[l];
                    bool sw = a > b2;
                    L[i] = sw ? b2 : a;
                    L[l] = sw ? a : b2;
                }
            }
        }
    }

    // Each partner lane writes 4 of the 16 outputs.
    float* o = out_knn + ((long long)b * N_ + q) * K_;
    #pragma unroll
    for (int k = 0; k < 4; ++k) {
        int kk = p * 4 + k;
        o[kk] = (float)(u32)(L[kk] & 0xFFFFFFFFu);
    }
    #undef TRY_APPEND
}

// ---------------------------------------------------------------------------
extern "C" void kernel_launch(void* const* d_in, const int* in_sizes, int n_in,
                              void* d_out, int out_size)
{
    const float* coords   = (const float*)d_in[0];
    const float* demands  = (const float*)d_in[1];
    const float* capacity = (const float*)d_in[2];
    const float* Wa       = (const float*)d_in[3];
    const float* ba       = (const float*)d_in[4];
    const float* W1       = (const float*)d_in[5];
    const float* b1       = (const float*)d_in[6];
    const float* W2       = (const float*)d_in[7];
    const float* b2       = (const float*)d_in[8];
    float* out = (float*)d_out;

    encode_kernel<<<dim3(N_ / 256, B_), 256>>>(coords, demands, capacity,
                                               Wa, ba, W1, b1, W2, b2, out);
    // B*N queries x 4 threads each; 128-thread blocks (32 queries/block)
    knn_kernel<<<dim3(B_ * N_ * 4 / 128), 128>>>(out + KNN_OFF);
}

// round 10
// speedup vs baseline: 1.2552x; 1.2552x over previous
#include <cuda_runtime.h>
#include <math.h>

#define B_   16
#define N_   2048
#define K_   16
#define EPS_ 1e-8f

// Output layout (tuple flattened in order):
//   psi_prime : B*N*2  floats  @ 0
//   features  : B*N*5  floats  @ 65536
//   knn_idx   : B*N*16 floats  @ 229376
#define PSI_OFF  0
#define FEAT_OFF (B_ * N_ * 2)
#define KNN_OFF  (B_ * N_ * 2 + B_ * N_ * 5)

typedef unsigned long long u64;
typedef unsigned int u32;

#define SENT 0xFFFFFFFFFFFFFFFFull
#define SUB_ (N_ / 2)          // candidates per thread (2 threads/query)
#define NWIN (SUB_ / 8)        // 8-candidate windows per thread (128)

// SOA candidate data for the KNN kernel.
__device__ float g_x [B_ * N_];
__device__ float g_y [B_ * N_];
__device__ float g_sq[B_ * N_];

// ---------------------------------------------------------------------------
// Kernel 1: features + encoder (tiny MLP) + SOA coord scratch.
// ---------------------------------------------------------------------------
__global__ void encode_kernel(const float* __restrict__ coords,
                              const float* __restrict__ demands,
                              const float* __restrict__ capacity,
                              const float* __restrict__ Wa,
                              const float* __restrict__ ba,
                              const float* __restrict__ W1,
                              const float* __restrict__ b1,
                              const float* __restrict__ W2,
                              const float* __restrict__ b2,
                              float* __restrict__ out)
{
    int b = blockIdx.y;
    int n = blockIdx.x * blockDim.x + threadIdx.x;
    if (n >= N_) return;

    __shared__ float sWa[10], sba[2], sW1[80], sb1[16], sW2[16], sb2_s;
    int t = threadIdx.x;
    if (t < 10) sWa[t] = Wa[t];
    if (t < 2)  sba[t] = ba[t];
    if (t < 80) sW1[t] = W1[t];
    if (t < 16) { sb1[t] = b1[t]; sW2[t] = W2[t]; }
    if (t == 0) sb2_s = b2[0];
    __syncthreads();

    const float* cp = coords + ((long long)b * N_ + n) * 2;
    float x = cp[0], y = cp[1];

    // SOA scratch for knn; sq = rn(rn(x*x) + rn(y*y)) (reference rounding)
    float sq = __fadd_rn(__fmul_rn(x, x), __fmul_rn(y, y));
    g_x [b * N_ + n] = x;
    g_y [b * N_ + n] = y;
    g_sq[b * N_ + n] = sq;

    float dx0 = coords[(long long)b * N_ * 2 + 0];
    float dy0 = coords[(long long)b * N_ * 2 + 1];
    float rx = x - dx0, ry = y - dy0;
    float dist = sqrtf(rx * rx + ry * ry + EPS_);
    float ang  = atan2f(ry, rx);
    float dem  = demands[(long long)b * N_ + n] / capacity[b];

    float f0 = x, f1 = y, f2 = dem, f3 = dist, f4 = ang;

    float* fo = out + FEAT_OFF + ((long long)b * N_ + n) * 5;
    fo[0] = f0; fo[1] = f1; fo[2] = f2; fo[3] = f3; fo[4] = f4;

    float p0 = sba[0] + f0*sWa[0] + f1*sWa[1] + f2*sWa[2] + f3*sWa[3] + f4*sWa[4];
    float p1 = sba[1] + f0*sWa[5] + f1*sWa[6] + f2*sWa[7] + f3*sWa[8] + f4*sWa[9];
    float nrm = sqrtf(p0 * p0 + p1 * p1);
    float inv = 1.0f / (nrm + EPS_);
    p0 *= inv; p1 *= inv;

    float theta = sb2_s;
    #pragma unroll
    for (int h = 0; h < 16; ++h) {
        const float* w = sW1 + h * 5;
        float a = sb1[h] + f0*w[0] + f1*w[1] + f2*w[2] + f3*w[3] + f4*w[4];
        theta += tanhf(a) * sW2[h];
    }
    float c = cosf(theta), s = sinf(theta);

    float* po = out + PSI_OFF + ((long long)b * N_ + n) * 2;
    po[0] = c * p0 - s * p1;
    po[1] = s * p0 + c * p1;
}

// ---------------------------------------------------------------------------
// KNN helpers
// ---------------------------------------------------------------------------

// Monotone map: float bits -> u32 whose unsigned order == float order.
__device__ __forceinline__ u32 fmap(u32 b) {
    return b ^ ((u32)((int)b >> 31) | 0x80000000u);
}

// Flush: convert raw (f32bits<<32|j) buffer entries to total-order keys,
// bitonic-sort-16, merge into sorted L (min-pair + clean), tighten tau.
// Exact ties: keys are (fmap(d2), j) lexicographic. (R7-proven.)
__device__ __forceinline__ void flush16(u64* L, const u64* lbuf, int& n,
                                        float& tau_f)
{
    u64 s[16];
    #pragma unroll
    for (int i = 0; i < 16; ++i) {
        u64 raw = lbuf[i];
        u64 key = ((u64)fmap((u32)(raw >> 32)) << 32) | (u32)raw;
        s[i] = (i < n) ? key : SENT;
    }

    // Bitonic sort 16, ascending.
    #pragma unroll
    for (int k = 2; k <= 16; k <<= 1) {
        #pragma unroll
        for (int j = k >> 1; j > 0; j >>= 1) {
            #pragma unroll
            for (int i = 0; i < 16; ++i) {
                int l = i ^ j;
                if (l > i) {
                    bool up = ((i & k) == 0);
                    u64 a = s[i], b = s[l];
                    bool sw = up ? (a > b) : (a < b);
                    s[i] = sw ? b : a;
                    s[l] = sw ? a : b;
                }
            }
        }
    }

    // Lowest 16 of (L asc, s asc): min-pair -> bitonic, then clean.
    #pragma unroll
    for (int i = 0; i < 16; ++i) {
        u64 a = L[i], b = s[15 - i];
        L[i] = (a < b) ? a : b;
    }
    #pragma unroll
    for (int j = 8; j > 0; j >>= 1) {
        #pragma unroll
        for (int i = 0; i < 16; ++i) {
            int l = i ^ j;
            if (l > i) {
                u64 a = L[i], b = L[l];
                bool sw = a > b;
                L[i] = sw ? b : a;
                L[l] = sw ? a : b;
            }
        }
    }

    // tau = d2 of current 16th (inverse fmap). If L[15] is still SENT
    // (possible once tau is shared and this lane admits <16 items), this
    // decodes to NaN; the fminf in the tau-share step then just takes the
    // partner's value (fminf(NaN, x) = x).
    u32 h = (u32)(L[15] >> 32);
    h = (h & 0x80000000u) ? (h ^ 0x80000000u) : ~h;
    tau_f = __uint_as_float(h);
    n = 0;
}

// d2 bit-exact with the reference:
//   t = rn(xq*xj); dot = fma(yq,yj,t); s = rn(sqq+sqj)
//   ref rn(s - rn(2*dot)) == rn(s - 2*dot) == fma(-2, dot, s)   [2*dot exact]
#define D2_OF(xv, yv, sv) \
    __fmaf_rn(-2.0f, __fmaf_rn(yq, (yv), __fmul_rn(xq, (xv))), \
              __fadd_rn(sqq, (sv)))

// ---------------------------------------------------------------------------
// Kernel 2: KNN top-16, buffered deferred selection, 2 threads per query.
// Identical to the R7 137.9us kernel except: after every warp-synchronized
// flush, tau is min-shared between the 2 partner lanes of each query.
// Validity: tau_shared >= global running 16th >= final global 16th, and the
// gate is '<=', so every final top-16 element is still admitted; the final
// partner merge takes the lowest-16 of the union. Ties exact via u64 keys.
// First flush fires while tau=inf (all candidates append), so both lanes'
// L are full after it -> at least one real tau at every share point.
// ---------------------------------------------------------------------------
__global__ void __launch_bounds__(128)
knn_kernel(float* __restrict__ out_knn)
{
    int qid = blockIdx.x * 64 + (threadIdx.x >> 1);  // global query id
    int p   = threadIdx.x & 1;                       // candidate-half
    int b   = qid >> 11;
    int q   = qid & (N_ - 1);

    const float* bx = g_x  + b * N_;
    const float* by = g_y  + b * N_;
    const float* bs = g_sq + b * N_;

    float xq  = __ldg(&bx[q]);
    float yq  = __ldg(&by[q]);
    float sqq = __ldg(&bs[q]);

    const float4* x4 = (const float4*)(bx + p * SUB_);
    const float4* y4 = (const float4*)(by + p * SUB_);
    const float4* s4 = (const float4*)(bs + p * SUB_);
    int jbase = p * SUB_;

    u64 L[16];
    #pragma unroll
    for (int k = 0; k < 16; ++k) L[k] = SENT;

    u64 lbuf[16];
    int n = 0;
    float tau_f = 3.4e38f;

    #define TRY_APPEND(ev, jv) \
        do { if ((ev) <= tau_f) \
            lbuf[n++] = ((u64)__float_as_uint(ev) << 32) | (u32)(jv); } while (0)

    for (int i = 0; i < NWIN; ++i) {
        float4 xa = __ldg(&x4[2 * i]);
        float4 xb = __ldg(&x4[2 * i + 1]);
        float4 ya = __ldg(&y4[2 * i]);
        float4 yb = __ldg(&y4[2 * i + 1]);
        float4 sa = __ldg(&s4[2 * i]);
        float4 sb = __ldg(&s4[2 * i + 1]);

        float e0 = D2_OF(xa.x, ya.x, sa.x);
        float e1 = D2_OF(xa.y, ya.y, sa.y);
        float e2 = D2_OF(xa.z, ya.z, sa.z);
        float e3 = D2_OF(xa.w, ya.w, sa.w);
        float e4 = D2_OF(xb.x, yb.x, sb.x);
        float e5 = D2_OF(xb.y, yb.y, sb.y);
        float e6 = D2_OF(xb.z, yb.z, sb.z);
        float e7 = D2_OF(xb.w, yb.w, sb.w);

        int j0 = jbase + 8 * i;
        // self-exclusion, one rare branch per 8-window
        if ((unsigned)(q - j0) < 8u) {
            int r = q - j0;
            if (r == 0) e0 = 2.0e30f;  if (r == 1) e1 = 2.0e30f;
            if (r == 2) e2 = 2.0e30f;  if (r == 3) e3 = 2.0e30f;
            if (r == 4) e4 = 2.0e30f;  if (r == 5) e5 = 2.0e30f;
            if (r == 6) e6 = 2.0e30f;  if (r == 7) e7 = 2.0e30f;
        }

        // '<=' so equal-d2/smaller-j candidates always enter; the u64-key
        // flush resolves ties exactly (top_k stable order).
        TRY_APPEND(e0, j0);     TRY_APPEND(e1, j0 + 1);
        TRY_APPEND(e2, j0 + 2); TRY_APPEND(e3, j0 + 3);
        TRY_APPEND(e4, j0 + 4); TRY_APPEND(e5, j0 + 5);
        TRY_APPEND(e6, j0 + 6); TRY_APPEND(e7, j0 + 7);

        // n <= 8 at entry, +8 -> 16 max: no overflow of lbuf[16].
        // Warp-synchronized flush keeps lanes aligned for the shfl below.
        if (__ballot_sync(0xffffffffu, n >= 9)) {
            flush16(L, lbuf, n, tau_f);
            // share tau with the partner lane (same query, other half):
            // min of the two local 16ths >= global running 16th.
            tau_f = fminf(tau_f, __shfl_xor_sync(0xffffffffu, tau_f, 1));
        }
    }

    flush16(L, lbuf, n, tau_f);   // drain

    // Merge partner halves (lane^1): min-pair vs partner's reversed sorted
    // list -> bitonic -> clean. Both lanes end with the identical top-16.
    #pragma unroll
    for (int i = 0; i < 16; ++i) {
        u64 other = __shfl_xor_sync(0xffffffffu, L[15 - i], 1);
        u64 a = L[i];
        L[i] = (a < other) ? a : other;
    }
    #pragma unroll
    for (int j = 8; j > 0; j >>= 1) {
        #pragma unroll
        for (int i = 0; i < 16; ++i) {
            int l = i ^ j;
            if (l > i) {
                u64 a = L[i], b2 = L[l];
                bool sw = a > b2;
                L[i] = sw ? b2 : a;
                L[l] = sw ? a : b2;
            }
        }
    }

    // Each partner lane writes half the 16 outputs.
    float* o = out_knn + ((long long)b * N_ + q) * K_;
    #pragma unroll
    for (int k = 0; k < 8; ++k) {
        int kk = p * 8 + k;
        o[kk] = (float)(u32)(L[kk] & 0xFFFFFFFFu);
    }
    #undef TRY_APPEND
}

// ---------------------------------------------------------------------------
extern "C" void kernel_launch(void* const* d_in, const int* in_sizes, int n_in,
                              void* d_out, int out_size)
{
    const float* coords   = (const float*)d_in[0];
    const float* demands  = (const float*)d_in[1];
    const float* capacity = (const float*)d_in[2];
    const float* Wa       = (const float*)d_in[3];
    const float* ba       = (const float*)d_in[4];
    const float* W1       = (const float*)d_in[5];
    const float* b1       = (const float*)d_in[6];
    const float* W2       = (const float*)d_in[7];
    const float* b2       = (const float*)d_in[8];
    float* out = (float*)d_out;

    encode_kernel<<<dim3(N_ / 256, B_), 256>>>(coords, demands, capacity,
                                               Wa, ba, W1, b1, W2, b2, out);
    // B*N queries x 2 threads each; 128-thread blocks (64 queries/block)
    knn_kernel<<<dim3(B_ * N_ * 2 / 128), 128>>>(out + KNN_OFF);
}